// round 2
// baseline (speedup 1.0000x reference)
#include <cuda_runtime.h>

// Problem constants (fixed by the reference):
//   S=3 symmetries, B=512 batches, N=1000 points, G=32 (G^3=32768 voxels)
//   GRID_MIN = -0.5 + 0.5/32 = -0.484375, scale = GRID/(2*GBOUND) = 32
#define S_SYM   3
#define B_BATCH 512
#define N_PTS   1000
#define G3      32768
#define SB_TOT  (S_SYM * B_BATCH)
#define GRID_MIN_F (-0.484375f)
#define NTHREADS 256

// Scratch for deterministic two-stage reduction: [0..1535]=plane loss sums,
// [1536..3071]=quat loss sums (per (s,b) block). Plus last-block ticket.
__device__ float g_partial[2 * SB_TOT];
__device__ unsigned int g_count;   // zero-initialized; reset by last block

__device__ __forceinline__ float fast_sqrt(float x) {
    float r;
    asm("sqrt.approx.f32 %0, %1;" : "=f"(r) : "f"(x));
    return r;
}

__device__ __forceinline__ float dist_term(float px, float py, float pz,
                                           const float* __restrict__ cpb,
                                           const float* __restrict__ vb)
{
    // vx = round(clip((p - GRID_MIN)*32, 0, 31)); rn = round-half-even == jnp.round
    float vx = fminf(fmaxf((px - GRID_MIN_F) * 32.0f, 0.0f), 31.0f);
    float vy = fminf(fmaxf((py - GRID_MIN_F) * 32.0f, 0.0f), 31.0f);
    float vz = fminf(fmaxf((pz - GRID_MIN_F) * 32.0f, 0.0f), 31.0f);
    int ix = __float2int_rn(vx);
    int iy = __float2int_rn(vy);
    int iz = __float2int_rn(vz);
    int lin = ix * 1024 + iy * 32 + iz;

    float mask = 1.0f - __ldg(vb + lin);
    const float* c = cpb + 3 * lin;
    float dx = (px - __ldg(c + 0)) * mask;
    float dy = (py - __ldg(c + 1)) * mask;
    float dz = (pz - __ldg(c + 2)) * mask;
    float n2 = dx * dx + dy * dy + dz * dz;
    return fast_sqrt(fmaxf(n2, 1e-30f));
}

__global__ __launch_bounds__(NTHREADS)
void sym_loss_kernel(const float* __restrict__ planes,
                     const float* __restrict__ quats,
                     const float* __restrict__ cps,
                     const float* __restrict__ pts,
                     const float* __restrict__ vol,
                     float* __restrict__ out)
{
    __shared__ float s_pts[3 * N_PTS];
    __shared__ float s_red[16];
    __shared__ int   s_is_last;

    const int sb = blockIdx.x;          // sb = s*B + b  (matches (S,B,4) layout)
    const int b  = sb & (B_BATCH - 1);

    const float4 pl = reinterpret_cast<const float4*>(planes)[sb];
    const float4 qq = reinterpret_cast<const float4*>(quats)[sb];
    const float* cpb = cps + (size_t)b * (3 * G3);
    const float* vb  = vol + (size_t)b * G3;
    const float* pb  = pts + (size_t)b * (3 * N_PTS);

    // Stage the batch's points in smem (fully coalesced global reads).
    for (int i = threadIdx.x; i < 3 * N_PTS; i += NTHREADS)
        s_pts[i] = pb[i];
    __syncthreads();

    // Plane reflect precompute
    const float inv = 1.0f / (pl.x * pl.x + pl.y * pl.y + pl.z * pl.z + 1e-8f);
    // Quat components (w,x,y,z); NOT normalized (matches reference)
    const float qw = qq.x, qx = qq.y, qy = qq.z, qz = qq.w;

    float lp = 0.0f, lq = 0.0f;
    #pragma unroll 2
    for (int n = threadIdx.x; n < N_PTS; n += NTHREADS) {
        float px = s_pts[3 * n + 0];
        float py = s_pts[3 * n + 1];
        float pz = s_pts[3 * n + 2];

        // --- plane reflection: p' = p - 2*(p.n + d)/(|n|^2+1e-8) * n
        float length = 2.0f * (px * pl.x + py * pl.y + pz * pl.z + pl.w);
        float t = length * inv;
        lp += dist_term(px - t * pl.x, py - t * pl.y, pz - t * pl.z, cpb, vb);

        // --- quat rotate: (q * (0,p) * conj(q)).xyz
        float tw = -qx * px - qy * py - qz * pz;
        float tx =  qw * px + qy * pz - qz * py;
        float ty =  qw * py - qx * pz + qz * px;
        float tz =  qw * pz + qx * py - qy * px;
        float rx = -tw * qx + tx * qw - ty * qz + tz * qy;
        float ry = -tw * qy + tx * qz + ty * qw - tz * qx;
        float rz = -tw * qz - tx * qy + ty * qx + tz * qw;
        lq += dist_term(rx, ry, rz, cpb, vb);
    }

    // Deterministic block reduction: warp shuffle then fixed-order smem sum.
    #pragma unroll
    for (int off = 16; off > 0; off >>= 1) {
        lp += __shfl_down_sync(0xffffffffu, lp, off);
        lq += __shfl_down_sync(0xffffffffu, lq, off);
    }
    const int lane = threadIdx.x & 31;
    const int wid  = threadIdx.x >> 5;
    if (lane == 0) { s_red[wid] = lp; s_red[8 + wid] = lq; }
    __syncthreads();
    if (threadIdx.x == 0) {
        float a = 0.0f, c2 = 0.0f;
        #pragma unroll
        for (int i = 0; i < 8; i++) { a += s_red[i]; c2 += s_red[8 + i]; }
        g_partial[sb] = a;
        g_partial[SB_TOT + sb] = c2;
        __threadfence();
        unsigned t = atomicAdd(&g_count, 1u);
        s_is_last = (t == SB_TOT - 1);
    }
    __syncthreads();

    // Last block to finish performs the final reduction in a FIXED order
    // (deterministic regardless of which block is last).
    if (s_is_last) {
        float a = 0.0f, c2 = 0.0f;
        for (int i = threadIdx.x; i < SB_TOT; i += NTHREADS) {
            a  += g_partial[i];
            c2 += g_partial[SB_TOT + i];
        }
        #pragma unroll
        for (int off = 16; off > 0; off >>= 1) {
            a  += __shfl_down_sync(0xffffffffu, a,  off);
            c2 += __shfl_down_sync(0xffffffffu, c2, off);
        }
        if (lane == 0) { s_red[wid] = a; s_red[8 + wid] = c2; }
        __syncthreads();
        if (threadIdx.x == 0) {
            float sa = 0.0f, sc = 0.0f;
            #pragma unroll
            for (int i = 0; i < 8; i++) { sa += s_red[i]; sc += s_red[8 + i]; }
            out[0] = sa * (1.0f / (float)SB_TOT);
            out[1] = sc * (1.0f / (float)SB_TOT);
            g_count = 0;   // reset for next graph replay
        }
    }
}

extern "C" void kernel_launch(void* const* d_in, const int* in_sizes, int n_in,
                              void* d_out, int out_size)
{
    const float* planes = (const float*)d_in[0];  // (3,512,4)
    const float* quats  = (const float*)d_in[1];  // (3,512,4)
    const float* cps    = (const float*)d_in[2];  // (512, 32768*3)
    const float* pts    = (const float*)d_in[3];  // (512,1000,3)
    const float* vol    = (const float*)d_in[4];  // (512,1,32,32,32)
    float* out = (float*)d_out;                   // [lp_mean, lq_mean]

    sym_loss_kernel<<<SB_TOT, NTHREADS>>>(planes, quats, cps, pts, vol, out);
}

// round 3
// speedup vs baseline: 1.3092x; 1.3092x over previous
#include <cuda_runtime.h>

// Problem constants (fixed by the reference):
//   S=3 symmetries, B=512 batches, N=1000 points, G=32 (G^3=32768 voxels)
//   GRID_MIN = -0.5 + 0.5/32 = -0.484375, scale = GRID/(2*GBOUND) = 32
#define S_SYM   3
#define B_BATCH 512
#define N_PTS   1000
#define G3      32768
#define SB_TOT  (S_SYM * B_BATCH)
#define GRID_MIN_F (-0.484375f)
#define NTHREADS 256

// Per-batch partial sums: [0..511]=plane, [512..1023]=quat. Plus ticket.
__device__ float g_partial[2 * B_BATCH];
__device__ unsigned int g_count;   // zero-initialized; reset by last block

__device__ __forceinline__ float fast_sqrt(float x) {
    float r;
    asm("sqrt.approx.f32 %0, %1;" : "=f"(r) : "f"(x));
    return r;
}

__device__ __forceinline__ int voxel_lin(float px, float py, float pz) {
    float vx = fminf(fmaxf((px - GRID_MIN_F) * 32.0f, 0.0f), 31.0f);
    float vy = fminf(fmaxf((py - GRID_MIN_F) * 32.0f, 0.0f), 31.0f);
    float vz = fminf(fmaxf((pz - GRID_MIN_F) * 32.0f, 0.0f), 31.0f);
    // __float2int_rn == round-half-even == jnp.round after clip
    return __float2int_rn(vx) * 1024 + __float2int_rn(vy) * 32 + __float2int_rn(vz);
}

__global__ __launch_bounds__(NTHREADS)
void sym_loss_kernel(const float* __restrict__ planes,
                     const float* __restrict__ quats,
                     const float* __restrict__ cps,
                     const float* __restrict__ pts,
                     const float* __restrict__ vol,
                     float* __restrict__ out)
{
    __shared__ float s_pts[3 * N_PTS];
    __shared__ float s_red[16];
    __shared__ int   s_is_last;

    const int b = blockIdx.x;                 // one block per batch
    const float* cpb = cps + (size_t)b * (3 * G3);
    const float* vb  = vol + (size_t)b * G3;
    const float* pb  = pts + (size_t)b * (3 * N_PTS);

    // Stage the batch's points once (shared across all 3 symmetries).
    for (int i = threadIdx.x; i < 3 * N_PTS; i += NTHREADS)
        s_pts[i] = pb[i];
    __syncthreads();

    float lp = 0.0f, lq = 0.0f;

    #pragma unroll
    for (int s = 0; s < S_SYM; s++) {
        const float4 pl = reinterpret_cast<const float4*>(planes)[s * B_BATCH + b];
        const float4 qq = reinterpret_cast<const float4*>(quats)[s * B_BATCH + b];
        const float inv = 1.0f / (pl.x * pl.x + pl.y * pl.y + pl.z * pl.z + 1e-8f);
        const float qw = qq.x, qx = qq.y, qy = qq.z, qz = qq.w;

        for (int n = threadIdx.x; n < N_PTS; n += NTHREADS) {
            float px = s_pts[3 * n + 0];
            float py = s_pts[3 * n + 1];
            float pz = s_pts[3 * n + 2];

            // --- plane reflection: p' = p - 2*(p.n + d)/(|n|^2+1e-8) * n
            float t = 2.0f * (px * pl.x + py * pl.y + pz * pl.z + pl.w) * inv;
            float ppx = px - t * pl.x;
            float ppy = py - t * pl.y;
            float ppz = pz - t * pl.z;

            // --- quat rotate: (q * (0,p) * conj(q)).xyz
            float tw = -qx * px - qy * py - qz * pz;
            float tx =  qw * px + qy * pz - qz * py;
            float ty =  qw * py - qx * pz + qz * px;
            float tz =  qw * pz + qx * py - qy * px;
            float rx = -tw * qx + tx * qw - ty * qz + tz * qy;
            float ry = -tw * qy + tx * qz + ty * qw - tz * qx;
            float rz = -tw * qz - tx * qy + ty * qx + tz * qw;

            // --- hoist ALL 8 gathers (both transforms) before consumption
            int lin_p = voxel_lin(ppx, ppy, ppz);
            int lin_q = voxel_lin(rx, ry, rz);
            const float* cp = cpb + 3 * lin_p;
            const float* cq = cpb + 3 * lin_q;
            float vmp = __ldg(vb + lin_p);
            float vmq = __ldg(vb + lin_q);
            float cp0 = __ldg(cp + 0), cp1 = __ldg(cp + 1), cp2 = __ldg(cp + 2);
            float cq0 = __ldg(cq + 0), cq1 = __ldg(cq + 1), cq2 = __ldg(cq + 2);

            float mp = 1.0f - vmp;
            float dx = (ppx - cp0) * mp;
            float dy = (ppy - cp1) * mp;
            float dz = (ppz - cp2) * mp;
            lp += fast_sqrt(fmaxf(dx * dx + dy * dy + dz * dz, 1e-30f));

            float mq = 1.0f - vmq;
            float ex = (rx - cq0) * mq;
            float ey = (ry - cq1) * mq;
            float ez = (rz - cq2) * mq;
            lq += fast_sqrt(fmaxf(ex * ex + ey * ey + ez * ez, 1e-30f));
        }
    }

    // Deterministic block reduction: warp shuffle then fixed-order smem sum.
    #pragma unroll
    for (int off = 16; off > 0; off >>= 1) {
        lp += __shfl_down_sync(0xffffffffu, lp, off);
        lq += __shfl_down_sync(0xffffffffu, lq, off);
    }
    const int lane = threadIdx.x & 31;
    const int wid  = threadIdx.x >> 5;
    if (lane == 0) { s_red[wid] = lp; s_red[8 + wid] = lq; }
    __syncthreads();
    if (threadIdx.x == 0) {
        float a = 0.0f, c2 = 0.0f;
        #pragma unroll
        for (int i = 0; i < 8; i++) { a += s_red[i]; c2 += s_red[8 + i]; }
        g_partial[b] = a;
        g_partial[B_BATCH + b] = c2;
        __threadfence();
        unsigned t = atomicAdd(&g_count, 1u);
        s_is_last = (t == B_BATCH - 1);
    }
    __syncthreads();

    // Last block performs the final reduction in a FIXED order (deterministic
    // regardless of which block finishes last).
    if (s_is_last) {
        float a = 0.0f, c2 = 0.0f;
        for (int i = threadIdx.x; i < B_BATCH; i += NTHREADS) {
            a  += g_partial[i];
            c2 += g_partial[B_BATCH + i];
        }
        #pragma unroll
        for (int off = 16; off > 0; off >>= 1) {
            a  += __shfl_down_sync(0xffffffffu, a,  off);
            c2 += __shfl_down_sync(0xffffffffu, c2, off);
        }
        if (lane == 0) { s_red[wid] = a; s_red[8 + wid] = c2; }
        __syncthreads();
        if (threadIdx.x == 0) {
            float sa = 0.0f, sc = 0.0f;
            #pragma unroll
            for (int i = 0; i < 8; i++) { sa += s_red[i]; sc += s_red[8 + i]; }
            out[0] = sa * (1.0f / (float)SB_TOT);
            out[1] = sc * (1.0f / (float)SB_TOT);
            g_count = 0;   // reset for next graph replay
        }
    }
}

extern "C" void kernel_launch(void* const* d_in, const int* in_sizes, int n_in,
                              void* d_out, int out_size)
{
    const float* planes = (const float*)d_in[0];  // (3,512,4)
    const float* quats  = (const float*)d_in[1];  // (3,512,4)
    const float* cps    = (const float*)d_in[2];  // (512, 32768*3)
    const float* pts    = (const float*)d_in[3];  // (512,1000,3)
    const float* vol    = (const float*)d_in[4];  // (512,1,32,32,32)
    float* out = (float*)d_out;                   // [lp_mean, lq_mean]

    sym_loss_kernel<<<B_BATCH, NTHREADS>>>(planes, quats, cps, pts, vol, out);
}

// round 4
// speedup vs baseline: 1.3524x; 1.0329x over previous
#include <cuda_runtime.h>

// Problem constants (fixed by the reference):
//   S=3 symmetries, B=512 batches, N=1000 points, G=32 (G^3=32768 voxels)
//   GRID_MIN = -0.5 + 0.5/32 = -0.484375, scale = GRID/(2*GBOUND) = 32
#define S_SYM   3
#define B_BATCH 512
#define N_PTS   1000
#define G3      32768
#define SB_TOT  (S_SYM * B_BATCH)
#define GRID_MIN_F (-0.484375f)
#define NTHREADS 512
#define NWARPS   (NTHREADS / 32)

// Per-batch partial sums: [0..511]=plane, [512..1023]=quat. Plus ticket.
__device__ float g_partial[2 * B_BATCH];
__device__ unsigned int g_count;   // zero-initialized; reset by last block

__device__ __forceinline__ float fast_sqrt(float x) {
    float r;
    asm("sqrt.approx.f32 %0, %1;" : "=f"(r) : "f"(x));
    return r;
}

__device__ __forceinline__ int voxel_lin(float px, float py, float pz) {
    float vx = fminf(fmaxf((px - GRID_MIN_F) * 32.0f, 0.0f), 31.0f);
    float vy = fminf(fmaxf((py - GRID_MIN_F) * 32.0f, 0.0f), 31.0f);
    float vz = fminf(fmaxf((pz - GRID_MIN_F) * 32.0f, 0.0f), 31.0f);
    // __float2int_rn == round-half-even == jnp.round after clip
    return __float2int_rn(vx) * 1024 + __float2int_rn(vy) * 32 + __float2int_rn(vz);
}

__global__ __launch_bounds__(NTHREADS)
void sym_loss_kernel(const float* __restrict__ planes,
                     const float* __restrict__ quats,
                     const float* __restrict__ cps,
                     const float* __restrict__ pts,
                     const float* __restrict__ vol,
                     float* __restrict__ out)
{
    __shared__ float s_pts[3 * N_PTS];
    __shared__ float s_red[2 * NWARPS];
    __shared__ int   s_is_last;

    const int b = blockIdx.x;                 // one block per batch
    const float* cpb = cps + (size_t)b * (3 * G3);
    const float* vb  = vol + (size_t)b * G3;
    const float* pb  = pts + (size_t)b * (3 * N_PTS);

    // Stage the batch's points once (shared across all 3 symmetries).
    // 3000 floats = 750 float4 — vector-wide coalesced copy.
    {
        const float4* src = reinterpret_cast<const float4*>(pb);
        float4* dst = reinterpret_cast<float4*>(s_pts);
        for (int i = threadIdx.x; i < (3 * N_PTS) / 4; i += NTHREADS)
            dst[i] = src[i];
    }
    __syncthreads();

    float lp = 0.0f, lq = 0.0f;

    #pragma unroll
    for (int s = 0; s < S_SYM; s++) {
        const float4 pl = reinterpret_cast<const float4*>(planes)[s * B_BATCH + b];
        const float4 qq = reinterpret_cast<const float4*>(quats)[s * B_BATCH + b];
        const float inv = 1.0f / (pl.x * pl.x + pl.y * pl.y + pl.z * pl.z + 1e-8f);
        const float qw = qq.x, qx = qq.y, qy = qq.z, qz = qq.w;

        for (int n = threadIdx.x; n < N_PTS; n += NTHREADS) {
            float px = s_pts[3 * n + 0];
            float py = s_pts[3 * n + 1];
            float pz = s_pts[3 * n + 2];

            // --- plane reflection: p' = p - 2*(p.n + d)/(|n|^2+1e-8) * n
            float t = 2.0f * (px * pl.x + py * pl.y + pz * pl.z + pl.w) * inv;
            float ppx = px - t * pl.x;
            float ppy = py - t * pl.y;
            float ppz = pz - t * pl.z;

            // --- quat rotate: (q * (0,p) * conj(q)).xyz
            float tw = -qx * px - qy * py - qz * pz;
            float tx =  qw * px + qy * pz - qz * py;
            float ty =  qw * py - qx * pz + qz * px;
            float tz =  qw * pz + qx * py - qy * px;
            float rx = -tw * qx + tx * qw - ty * qz + tz * qy;
            float ry = -tw * qy + tx * qz + ty * qw - tz * qx;
            float rz = -tw * qz - tx * qy + ty * qx + tz * qw;

            // --- hoist ALL 8 gathers (both transforms) before consumption
            int lin_p = voxel_lin(ppx, ppy, ppz);
            int lin_q = voxel_lin(rx, ry, rz);
            const float* cp = cpb + 3 * lin_p;
            const float* cq = cpb + 3 * lin_q;
            float vmp = __ldg(vb + lin_p);
            float vmq = __ldg(vb + lin_q);
            float cp0 = __ldg(cp + 0), cp1 = __ldg(cp + 1), cp2 = __ldg(cp + 2);
            float cq0 = __ldg(cq + 0), cq1 = __ldg(cq + 1), cq2 = __ldg(cq + 2);

            float mp = 1.0f - vmp;
            float dx = (ppx - cp0) * mp;
            float dy = (ppy - cp1) * mp;
            float dz = (ppz - cp2) * mp;
            lp += fast_sqrt(fmaxf(dx * dx + dy * dy + dz * dz, 1e-30f));

            float mq = 1.0f - vmq;
            float ex = (rx - cq0) * mq;
            float ey = (ry - cq1) * mq;
            float ez = (rz - cq2) * mq;
            lq += fast_sqrt(fmaxf(ex * ex + ey * ey + ez * ez, 1e-30f));
        }
    }

    // Deterministic block reduction: warp shuffle then fixed-order smem sum.
    #pragma unroll
    for (int off = 16; off > 0; off >>= 1) {
        lp += __shfl_down_sync(0xffffffffu, lp, off);
        lq += __shfl_down_sync(0xffffffffu, lq, off);
    }
    const int lane = threadIdx.x & 31;
    const int wid  = threadIdx.x >> 5;
    if (lane == 0) { s_red[wid] = lp; s_red[NWARPS + wid] = lq; }
    __syncthreads();
    if (threadIdx.x == 0) {
        float a = 0.0f, c2 = 0.0f;
        #pragma unroll
        for (int i = 0; i < NWARPS; i++) { a += s_red[i]; c2 += s_red[NWARPS + i]; }
        g_partial[b] = a;
        g_partial[B_BATCH + b] = c2;
        __threadfence();
        unsigned t = atomicAdd(&g_count, 1u);
        s_is_last = (t == B_BATCH - 1);
    }
    __syncthreads();

    // Last block performs the final reduction in a FIXED order (deterministic
    // regardless of which block finishes last).
    if (s_is_last) {
        float a = 0.0f, c2 = 0.0f;
        for (int i = threadIdx.x; i < B_BATCH; i += NTHREADS) {
            a  += g_partial[i];
            c2 += g_partial[B_BATCH + i];
        }
        #pragma unroll
        for (int off = 16; off > 0; off >>= 1) {
            a  += __shfl_down_sync(0xffffffffu, a,  off);
            c2 += __shfl_down_sync(0xffffffffu, c2, off);
        }
        if (lane == 0) { s_red[wid] = a; s_red[NWARPS + wid] = c2; }
        __syncthreads();
        if (threadIdx.x == 0) {
            float sa = 0.0f, sc = 0.0f;
            #pragma unroll
            for (int i = 0; i < NWARPS; i++) { sa += s_red[i]; sc += s_red[NWARPS + i]; }
            out[0] = sa * (1.0f / (float)SB_TOT);
            out[1] = sc * (1.0f / (float)SB_TOT);
            g_count = 0;   // reset for next graph replay
        }
    }
}

extern "C" void kernel_launch(void* const* d_in, const int* in_sizes, int n_in,
                              void* d_out, int out_size)
{
    const float* planes = (const float*)d_in[0];  // (3,512,4)
    const float* quats  = (const float*)d_in[1];  // (3,512,4)
    const float* cps    = (const float*)d_in[2];  // (512, 32768*3)
    const float* pts    = (const float*)d_in[3];  // (512,1000,3)
    const float* vol    = (const float*)d_in[4];  // (512,1,32,32,32)
    float* out = (float*)d_out;                   // [lp_mean, lq_mean]

    sym_loss_kernel<<<B_BATCH, NTHREADS>>>(planes, quats, cps, pts, vol, out);
}